// round 11
// baseline (speedup 1.0000x reference)
#include <cuda_runtime.h>
#include <cuda_bf16.h>
#include <cstdint>
#include <cstddef>

#define B_   32
#define T_   128
#define H_   512
#define V_   32000
#define G_   2048      // 4*H
#define KBIG 1536      // 3*H (hi|lo|hi split)
#define NCTA_REC 128

typedef unsigned long long ull;

// ---------------- packed f32x2 helpers ----------------
__device__ __forceinline__ ull pk2(float lo, float hi) {
    ull r; asm("mov.b64 %0, {%1, %2};" : "=l"(r) : "f"(lo), "f"(hi)); return r;
}
__device__ __forceinline__ void upk2(ull v, float& lo, float& hi) {
    asm("mov.b64 {%0, %1}, %2;" : "=f"(lo), "=f"(hi) : "l"(v));
}
__device__ __forceinline__ void fma2(ull& d, ull a, ull b) {
    asm("fma.rn.f32x2 %0, %1, %2, %0;" : "+l"(d) : "l"(a), "l"(b));
}

// ---------------- device scratch ----------------
__device__ float g_XW[(size_t)T_ * B_ * G_];
__device__ float g_Hst[(size_t)B_ * T_ * H_];
__device__ float g_hbuf[2][H_ * B_];
__device__ float g_bias2[G_];
__device__ int   g_tok[T_ * B_];
__device__ unsigned g_bar;                 // grid barrier counter (reset in prep)
__device__ __nv_bfloat16 g_Abig[(size_t)B_ * T_ * KBIG];   // [4096][1536] = [hi|lo|hi]
__device__ __nv_bfloat16 g_Bbig[(size_t)V_ * KBIG];        // [32000][1536] = [hi|hi|lo]

// ---------------- misc helpers ----------------
__device__ __forceinline__ uint32_t smem_u32(const void* p) {
    uint32_t a; asm("{ .reg .u64 t; cvta.to.shared.u64 t, %1; cvt.u32.u64 %0, t; }" : "=r"(a) : "l"(p));
    return a;
}
__device__ __forceinline__ uint32_t swz(uint32_t x) { return x ^ ((x >> 3) & 0x70); }
__device__ __forceinline__ void cp16(uint32_t dst, const void* src) {
    unsigned long long g;
    asm("cvta.to.global.u64 %0, %1;" : "=l"(g) : "l"(src));
    asm volatile("cp.async.cg.shared.global [%0], [%1], 16;" :: "r"(dst), "l"(g));
}
__device__ __forceinline__ void mma16816(float* c, const unsigned* a, const unsigned* b) {
    asm volatile(
        "mma.sync.aligned.m16n8k16.row.col.f32.bf16.bf16.f32 "
        "{%0,%1,%2,%3}, {%4,%5,%6,%7}, {%8,%9}, {%0,%1,%2,%3};"
        : "+f"(c[0]), "+f"(c[1]), "+f"(c[2]), "+f"(c[3])
        : "r"(a[0]), "r"(a[1]), "r"(a[2]), "r"(a[3]), "r"(b[0]), "r"(b[1]));
}

// ---------------- phase 1: prep ----------------
__global__ void prep_kernel(const void* __restrict__ target,
                            const float* __restrict__ b_ih,
                            const float* __restrict__ b_hh,
                            const float* __restrict__ enc)
{
    __shared__ int is64;
    if (threadIdx.x == 0) {
        const unsigned* w = (const unsigned*)target;
        int f = 1;
        for (int i = 1; i <= 16; ++i) if (w[2 * i + 1] != 0u) f = 0;
        is64 = f;
    }
    __syncthreads();
    if (blockIdx.x == 0 && threadIdx.x == 0) g_bar = 0u;   // deterministic per call

    const long long* t64 = (const long long*)target;
    const int*       t32 = (const int*)target;
    int tid = blockIdx.x * blockDim.x + threadIdx.x;
    int nth = gridDim.x * blockDim.x;

    for (int m = tid; m < T_ * B_; m += nth) {
        int t = m / B_, b = m % B_;
        int tok;
        if (t == 0) tok = 1;
        else tok = is64 ? (int)t64[(size_t)b * T_ + (t - 1)] : t32[(size_t)b * T_ + (t - 1)];
        g_tok[m] = tok;
    }
    for (int j = tid; j < G_; j += nth) g_bias2[j] = b_ih[j] + b_hh[j];
    for (int i = tid; i < H_ * B_; i += nth) {
        int k = i >> 5, b = i & 31;
        g_hbuf[0][i] = enc[(size_t)b * H_ + k];
    }
}

// ---------------- bf16 hi/lo conversions ----------------
__device__ __forceinline__ void split4(float4 v, ull& hiP, ull& loP) {
    union { __nv_bfloat16 h[4]; ull u; } Hh, Ll;
    float x[4] = {v.x, v.y, v.z, v.w};
#pragma unroll
    for (int j = 0; j < 4; ++j) {
        __nv_bfloat16 h = __float2bfloat16(x[j]);
        Hh.h[j] = h;
        Ll.h[j] = __float2bfloat16(x[j] - __bfloat162float(h));
    }
    hiP = Hh.u; loP = Ll.u;
}

__global__ void convB_kernel(const float* __restrict__ E) {
    size_t i4 = (size_t)blockIdx.x * blockDim.x + threadIdx.x;
    if (i4 >= (size_t)V_ * (H_ / 4)) return;
    size_t r = i4 / (H_ / 4);
    int k = (int)(i4 % (H_ / 4)) * 4;
    float4 v = *(const float4*)&E[r * H_ + k];
    ull hiP, loP; split4(v, hiP, loP);
    __nv_bfloat16* row = g_Bbig + r * KBIG;
    *(ull*)(row + k)        = hiP;   // Bhi
    *(ull*)(row + 512 + k)  = hiP;   // Bhi
    *(ull*)(row + 1024 + k) = loP;   // Blo
}

__global__ void convA_kernel() {
    size_t i4 = (size_t)blockIdx.x * blockDim.x + threadIdx.x;
    if (i4 >= (size_t)B_ * T_ * (H_ / 4)) return;
    size_t r = i4 / (H_ / 4);
    int k = (int)(i4 % (H_ / 4)) * 4;
    float4 v = *(const float4*)&g_Hst[r * H_ + k];
    ull hiP, loP; split4(v, hiP, loP);
    __nv_bfloat16* row = g_Abig + r * KBIG;
    *(ull*)(row + k)        = hiP;   // Ahi
    *(ull*)(row + 512 + k)  = loP;   // Alo
    *(ull*)(row + 1024 + k) = hiP;   // Ahi
}

// ---------------- phase 2: XW GEMM (fp32) ----------------
__global__ void __launch_bounds__(256) gemm_nt_kernel(
    const float* __restrict__ Aext, const float* __restrict__ Bm,
    int M, int N, int K)
{
    __shared__ float As[2][8][128];
    __shared__ float Bs[2][8][128];
    const float* bias = g_bias2;
    float* C = g_XW;

    int tid = threadIdx.x;
    int m0 = blockIdx.y * 128, n0 = blockIdx.x * 128;
    int lm = tid >> 1, lk = (tid & 1) * 4;

    int arow = g_tok[m0 + lm];
    const float* Ap = Aext + (size_t)arow * K + lk;
    const float* Bp = Bm + (size_t)(n0 + lm) * K + lk;

    {
        float4 va = *(const float4*)Ap;
        float4 vb = *(const float4*)Bp;
        As[0][lk + 0][lm] = va.x; As[0][lk + 1][lm] = va.y;
        As[0][lk + 2][lm] = va.z; As[0][lk + 3][lm] = va.w;
        Bs[0][lk + 0][lm] = vb.x; Bs[0][lk + 1][lm] = vb.y;
        Bs[0][lk + 2][lm] = vb.z; Bs[0][lk + 3][lm] = vb.w;
    }
    __syncthreads();

    int tx = tid & 15, ty = tid >> 4;
    ull acc[8][4];
#pragma unroll
    for (int i = 0; i < 8; ++i)
#pragma unroll
        for (int j = 0; j < 4; ++j) acc[i][j] = 0ull;

    int nstage = K / 8, buf = 0;
    for (int s = 0; s < nstage; ++s) {
        float4 va, vb;
        if (s + 1 < nstage) {
            va = *(const float4*)(Ap + (size_t)(s + 1) * 8);
            vb = *(const float4*)(Bp + (size_t)(s + 1) * 8);
        }
#pragma unroll
        for (int k = 0; k < 8; ++k) {
            float4 a0 = *(const float4*)&As[buf][k][ty * 8];
            float4 a1 = *(const float4*)&As[buf][k][ty * 8 + 4];
            float4 b0 = *(const float4*)&Bs[buf][k][tx * 4];
            float4 b1 = *(const float4*)&Bs[buf][k][tx * 4 + 64];
            ull bp0 = pk2(b0.x, b0.y), bp1 = pk2(b0.z, b0.w);
            ull bp2 = pk2(b1.x, b1.y), bp3 = pk2(b1.z, b1.w);
            float av[8] = {a0.x, a0.y, a0.z, a0.w, a1.x, a1.y, a1.z, a1.w};
#pragma unroll
            for (int i = 0; i < 8; ++i) {
                ull ad = pk2(av[i], av[i]);
                fma2(acc[i][0], ad, bp0);
                fma2(acc[i][1], ad, bp1);
                fma2(acc[i][2], ad, bp2);
                fma2(acc[i][3], ad, bp3);
            }
        }
        if (s + 1 < nstage) {
            int nb = buf ^ 1;
            As[nb][lk + 0][lm] = va.x; As[nb][lk + 1][lm] = va.y;
            As[nb][lk + 2][lm] = va.z; As[nb][lk + 3][lm] = va.w;
            Bs[nb][lk + 0][lm] = vb.x; Bs[nb][lk + 1][lm] = vb.y;
            Bs[nb][lk + 2][lm] = vb.z; Bs[nb][lk + 3][lm] = vb.w;
            __syncthreads();
            buf = nb;
        }
    }

    int nA = n0 + tx * 4;
    float bv[8];
#pragma unroll
    for (int c = 0; c < 4; ++c) { bv[c] = bias[nA + c]; bv[4 + c] = bias[nA + 64 + c]; }
#pragma unroll
    for (int i = 0; i < 8; ++i) {
        int m = m0 + ty * 8 + i;
        float r[8];
        upk2(acc[i][0], r[0], r[1]); upk2(acc[i][1], r[2], r[3]);
        upk2(acc[i][2], r[4], r[5]); upk2(acc[i][3], r[6], r[7]);
        float4 o0 = make_float4(r[0] + bv[0], r[1] + bv[1], r[2] + bv[2], r[3] + bv[3]);
        float4 o1 = make_float4(r[4] + bv[4], r[5] + bv[5], r[6] + bv[6], r[7] + bv[7]);
        *(float4*)(C + (size_t)m * N + nA)      = o0;
        *(float4*)(C + (size_t)m * N + nA + 64) = o1;
    }
}

// ---------------- phase 3: persistent LSTM recurrence ----------------
// Thread tile: 4 gate-rows x 8 batches, un-duplicated W (LDS.128 of 4 w +
// in-loop pk2), k split into 16 segments of 2x16 (one 16-run per h chunk).
// Smem: Ws[512][16] 32KB | hs[512][32] 64KB | red[16][16][32] 32KB | gsm 2KB
__device__ __forceinline__ float sigm(float x) { return 1.0f / (1.0f + expf(-x)); }

__global__ void __launch_bounds__(256, 1) lstm_persist_kernel(
    const float* __restrict__ W_hh, const float* __restrict__ enc)
{
    extern __shared__ float smf[];
    float* Ws  = smf;                      // [512][16]
    float* hs  = smf + 8192;               // [512][32]
    float* red = smf + 24576;              // [16][16][32]
    float* gsm = smf + 32768;              // [16][32]

    int cta = blockIdx.x;
    int tid = threadIdx.x;
    uint32_t hsm = smem_u32(hs);

    // ---- stage W_hh rows once (un-duplicated) ----
#pragma unroll
    for (int jl = 0; jl < 16; ++jl) {
        int j = (jl >> 2) * H_ + cta * 4 + (jl & 3);
#pragma unroll
        for (int it = 0; it < 2; ++it) {
            int k = it * 256 + tid;
            Ws[k * 16 + jl] = W_hh[(size_t)j * H_ + k];
        }
    }

    // compute role: g = (jg, bg) tile id, kq = k segment
    int g  = tid >> 4;
    int kq = tid & 15;
    int jg = g >> 2, bg = g & 3;
    int jlb = jg * 4;       // 4 gate rows jlb..jlb+3
    int bb  = bg * 8;       // 8 batches bb..bb+7

    // reduce role
    int rjl = tid >> 4, rb0 = (tid & 15) * 2;
    int rj  = (rjl >> 2) * H_ + cta * 4 + (rjl & 3);

    // elementwise role
    int hl = tid >> 5, eb = tid & 31;
    int ek = cta * 4 + hl;
    float creg = 0.f;
    if (tid < 128) creg = enc[(size_t)eb * H_ + ek];

    for (int t = 0; t < T_; ++t) {
        float xw0 = g_XW[((size_t)t * B_ + rb0) * G_ + rj];
        float xw1 = g_XW[((size_t)t * B_ + rb0 + 1) * G_ + rj];

        // stage h in two cp.async chunks (k [0,256) then [256,512))
        {
            const float4* src = (const float4*)g_hbuf[t & 1];
#pragma unroll
            for (int i = 0; i < 8; ++i)
                cp16(hsm + (uint32_t)(tid + i * 256) * 16u, src + tid + i * 256);
            asm volatile("cp.async.commit_group;" ::: "memory");
#pragma unroll
            for (int i = 0; i < 8; ++i)
                cp16(hsm + (uint32_t)(2048 + tid + i * 256) * 16u,
                     src + 2048 + tid + i * 256);
            asm volatile("cp.async.commit_group;" ::: "memory");
        }

        ull acc[4][4];
#pragma unroll
        for (int j = 0; j < 4; ++j)
#pragma unroll
            for (int p = 0; p < 4; ++p) acc[j][p] = 0ull;

        asm volatile("cp.async.wait_group 1;" ::: "memory");
        __syncthreads();
        {
            int k0 = kq * 16;
#pragma unroll 8
            for (int kk = 0; kk < 16; ++kk) {
                int k = k0 + kk;
                float4 w4 = *(const float4*)&Ws[k * 16 + jlb];
                ulonglong2 hA = *(const ulonglong2*)&hs[k * 32 + bb];
                ulonglong2 hB = *(const ulonglong2*)&hs[k * 32 + bb + 4];
                ull w0 = pk2(w4.x, w4.x), w1 = pk2(w4.y, w4.y);
                ull w2 = pk2(w4.z, w4.z), w3 = pk2(w4.w, w4.w);
                fma2(acc[0][0], hA.x, w0); fma2(acc[0][1], hA.y, w0);
                fma2(acc[0][2], hB.x, w0); fma2(acc[0][3], hB.y, w0);
                fma2(acc[1][0], hA.x, w1); fma2(acc[1][1], hA.y, w1);
                fma2(acc[1][2], hB.x, w1); fma2(acc[1][3], hB.y, w1);
                fma2(acc[2][0], hA.x, w2); fma2(acc[2][1], hA.y, w2);
                fma2(acc[2][2], hB.x, w2); fma2(acc[2][3], hB.y, w2);
                fma2(acc[3][0], hA.x, w3); fma2(acc[3][1], hA.y, w3);
                fma2(acc[3][2], hB.x, w3); fma2(acc[3][3], hB.y, w3);
            }
        }
        asm volatile("cp.async.wait_group 0;" ::: "memory");
        __syncthreads();
        {
            int k0 = 256 + kq * 16;
#pragma unroll 8
            for (int kk = 0; kk < 16; ++kk) {
                int k = k0 + kk;
                float4 w4 = *(const float4*)&Ws[k * 16 + jlb];
                ulonglong2 hA = *(const ulonglong2*)&hs[k * 32 + bb];
                ulonglong2 hB = *(const ulonglong2*)&hs[k * 32 + bb + 4];
                ull w0 = pk2(w4.x, w4.x), w1 = pk2(w4.y, w4.y);
                ull w2 = pk2(w4.z, w4.z), w3 = pk2(w4.w, w4.w);
                fma2(acc[0][0], hA.x, w0); fma2(acc[0][1], hA.y, w0);
                fma2(acc[0][2], hB.x, w0); fma2(acc[0][3], hB.y, w0);
                fma2(acc[1][0], hA.x, w1); fma2(acc[1][1], hA.y, w1);
                fma2(acc[1][2], hB.x, w1); fma2(acc[1][3], hB.y, w1);
                fma2(acc[2][0], hA.x, w2); fma2(acc[2][1], hA.y, w2);
                fma2(acc[2][2], hB.x, w2); fma2(acc[2][3], hB.y, w2);
                fma2(acc[3][0], hA.x, w3); fma2(acc[3][1], hA.y, w3);
                fma2(acc[3][2], hB.x, w3); fma2(acc[3][3], hB.y, w3);
            }
        }

        // partials -> red[kq][jl][b]
#pragma unroll
        for (int j = 0; j < 4; ++j)
#pragma unroll
            for (int p = 0; p < 4; ++p)
                *(ull*)&red[(kq * 16 + jlb + j) * 32 + bb + p * 2] = acc[j][p];
        __syncthreads();

        // reduce 16 segments + XW -> gates
        {
            float s0 = xw0, s1 = xw1;
#pragma unroll
            for (int qq = 0; qq < 16; ++qq) {
                float2 v = *(float2*)&red[(qq * 16 + rjl) * 32 + rb0];
                s0 += v.x; s1 += v.y;
            }
            *(float2*)&gsm[rjl * 32 + rb0] = make_float2(s0, s1);
        }
        __syncthreads();

        if (tid < 128) {
            float gi = gsm[(0 * 4 + hl) * 32 + eb];
            float gf = gsm[(1 * 4 + hl) * 32 + eb];
            float gg = gsm[(2 * 4 + hl) * 32 + eb];
            float go = gsm[(3 * 4 + hl) * 32 + eb];
            float cnew = sigm(gf) * creg + sigm(gi) * tanhf(gg);
            float hnew = sigm(go) * tanhf(cnew);
            creg = cnew;
            __stcg(&g_hbuf[(t + 1) & 1][cta * 128 + tid], hnew);
            g_Hst[((size_t)eb * T_ + t) * H_ + ek] = hnew;
        }

        // ---- grid barrier (single atomic arrival per CTA; R7-proven) ----
        __threadfence();
        __syncthreads();
        if (tid == 0) {
            unsigned arrived = atomicAdd(&g_bar, 1u) + 1u;
            unsigned target = (unsigned)NCTA_REC * (unsigned)(t + 1);
            while (arrived < target)
                arrived = *(volatile unsigned*)&g_bar;
        }
        __syncthreads();
    }
}

// ---------------- phase 4: logits via mma.sync bf16 (3-term hi/lo) ----------------
#define LSTG 49152u   // per-stage: A 16KB + B 32KB
#define LNIT 24       // KBIG / 64

__device__ __forceinline__ void lstage(uint32_t sb, int buf, int s,
                                       int m0, int n0, int tid) {
    uint32_t base = (uint32_t)buf * LSTG;
#pragma unroll
    for (int i = 0; i < 2; ++i) {              // A: 1024 x 16B
        int cid = i * 512 + tid;
        int r = cid >> 3, c = cid & 7;
        cp16(sb + base + swz((uint32_t)(r * 128 + c * 16)),
             &g_Abig[(size_t)(m0 + r) * KBIG + s * 64 + c * 8]);
    }
#pragma unroll
    for (int i = 0; i < 4; ++i) {              // B: 2048 x 16B
        int cid = i * 512 + tid;
        int r = cid >> 3, c = cid & 7;
        cp16(sb + base + 16384u + swz((uint32_t)(r * 128 + c * 16)),
             &g_Bbig[(size_t)(n0 + r) * KBIG + s * 64 + c * 8]);
    }
    asm volatile("cp.async.commit_group;" ::: "memory");
}

__global__ void __launch_bounds__(512, 1) logits_mma_kernel(
    const float* __restrict__ b_out, float* __restrict__ out)
{
    extern __shared__ char smc[];
    uint32_t sb = smem_u32(smc);

    int tid = threadIdx.x;
    int lane = tid & 31, wid = tid >> 5;
    int wm = wid & 1, wn = wid >> 1;

    int blk = blockIdx.x;
    int nt = blk >> 5, mt = blk & 31;
    int m0 = mt * 128, n0 = nt * 256;

    int arow = wm * 64 + ((lane >> 3) & 1) * 8 + (lane & 7);
    int akb  = ((lane >> 4) & 1) * 16;
    int brl  = lane & 15;
    int brow = wn * 32 + (brl & 7);
    int bkb  = ((brl >> 3) & 1) * 16;

    float acc[4][4][4];
#pragma unroll
    for (int i = 0; i < 4; ++i)
#pragma unroll
        for (int j = 0; j < 4; ++j)
#pragma unroll
            for (int k = 0; k < 4; ++k) acc[i][j][k] = 0.f;

    lstage(sb, 0, 0, m0, n0, tid);
    lstage(sb, 1, 1, m0, n0, tid);

    for (int s = 0; s < LNIT; ++s) {
        int buf = s % 3;
        if (s + 1 < LNIT) asm volatile("cp.async.wait_group 1;" ::: "memory");
        else              asm volatile("cp.async.wait_group 0;" ::: "memory");
        __syncthreads();
        if (s + 2 < LNIT) lstage(sb, (s + 2) % 3, s + 2, m0, n0, tid);

        uint32_t Ab = sb + (uint32_t)buf * LSTG;
        uint32_t Bb = Ab + 16384u;
#pragma unroll
        for (int ks = 0; ks < 4; ++ks) {
            unsigned af[4][4];
#pragma unroll
            for (int mf = 0; mf < 4; ++mf) {
                uint32_t a = Ab + swz((uint32_t)((arow + mf * 16) * 128 + ks * 32 + akb));
                asm volatile("ldmatrix.sync.aligned.m8n8.x4.shared.b16 {%0,%1,%2,%3}, [%4];"
                    : "=r"(af[mf][0]), "=r"(af[mf][1]), "=r"(af[mf][2]), "=r"(af[mf][3])
                    : "r"(a));
            }
            unsigned bf[4][2];
#pragma unroll
            for (int nf = 0; nf < 4; ++nf) {
                uint32_t a = Bb + swz((uint32_t)((brow + nf * 8) * 128 + ks * 32 + bkb));
                asm volatile("ldmatrix.sync.aligned.m8n8.x2.shared.b16 {%0,%1}, [%2];"
                    : "=r"(bf[nf][0]), "=r"(bf[nf][1]) : "r"(a));
            }
#pragma unroll
            for (int mf = 0; mf < 4; ++mf)
#pragma unroll
                for (int nf = 0; nf < 4; ++nf)
                    mma16816(acc[mf][nf], af[mf], bf[nf]);
        }
    }

    // epilogue: bias + float2 stores
    int ncol0 = n0 + wn * 32;
    float bv[4][2];
#pragma unroll
    for (int nf = 0; nf < 4; ++nf) {
        int c = ncol0 + nf * 8 + (lane & 3) * 2;
        bv[nf][0] = b_out[c]; bv[nf][1] = b_out[c + 1];
    }
#pragma unroll
    for (int mf = 0; mf < 4; ++mf) {
        int mrow = m0 + wm * 64 + mf * 16 + (lane >> 2);
#pragma unroll
        for (int nf = 0; nf < 4; ++nf) {
            int c = ncol0 + nf * 8 + (lane & 3) * 2;
            float2 v0 = make_float2(acc[mf][nf][0] + bv[nf][0],
                                    acc[mf][nf][1] + bv[nf][1]);
            float2 v1 = make_float2(acc[mf][nf][2] + bv[nf][0],
                                    acc[mf][nf][3] + bv[nf][1]);
            *(float2*)(out + (size_t)mrow * V_ + c)       = v0;
            *(float2*)(out + (size_t)(mrow + 8) * V_ + c) = v1;
        }
    }
}

// ---------------- launcher ----------------
extern "C" void kernel_launch(void* const* d_in, const int* in_sizes, int n_in,
                              void* d_out, int out_size)
{
    const float* enc    = (const float*)d_in[0];
    const void*  target = d_in[1];
    const float* E      = (const float*)d_in[2];
    const float* W_ih   = (const float*)d_in[3];
    const float* W_hh   = (const float*)d_in[4];
    const float* b_ih   = (const float*)d_in[5];
    const float* b_hh   = (const float*)d_in[6];
    const float* b_out  = (const float*)d_in[7];
    float* out = (float*)d_out;

    const int REC_SMEM = (8192 + 16384 + 8192 + 512) * 4;    // 133120 B
    cudaFuncSetAttribute(lstm_persist_kernel,
                         cudaFuncAttributeMaxDynamicSharedMemorySize, REC_SMEM);
    const int LOG_SMEM = 3 * (int)LSTG;                      // 147456 B
    cudaFuncSetAttribute(logits_mma_kernel,
                         cudaFuncAttributeMaxDynamicSharedMemorySize, LOG_SMEM);

    prep_kernel<<<64, 256>>>(target, b_ih, b_hh, enc);

    convB_kernel<<<(V_ * (H_ / 4) + 255) / 256, 256>>>(E);

    {
        dim3 grid(G_ / 128, (T_ * B_) / 128);
        gemm_nt_kernel<<<grid, 256>>>(E, W_ih, T_ * B_, G_, H_);
    }

    lstm_persist_kernel<<<NCTA_REC, 256, REC_SMEM>>>(W_hh, enc);

    convA_kernel<<<(B_ * T_ * (H_ / 4) + 255) / 256, 256>>>();

    logits_mma_kernel<<<32 * (V_ / 256), 512, LOG_SMEM>>>(b_out, out);
}

// round 14
// speedup vs baseline: 1.6634x; 1.6634x over previous
#include <cuda_runtime.h>
#include <cuda_bf16.h>
#include <cstdint>
#include <cstddef>

#define B_   32
#define T_   128
#define H_   512
#define V_   32000
#define G_   2048      // 4*H
#define KBIG 1536      // 3*H (hi|lo|hi split)
#define NCTA_REC 128

typedef unsigned long long ull;

// ---------------- packed f32x2 helpers ----------------
__device__ __forceinline__ ull pk2(float lo, float hi) {
    ull r; asm("mov.b64 %0, {%1, %2};" : "=l"(r) : "f"(lo), "f"(hi)); return r;
}
__device__ __forceinline__ void upk2(ull v, float& lo, float& hi) {
    asm("mov.b64 {%0, %1}, %2;" : "=f"(lo), "=f"(hi) : "l"(v));
}
__device__ __forceinline__ void fma2(ull& d, ull a, ull b) {
    asm("fma.rn.f32x2 %0, %1, %2, %0;" : "+l"(d) : "l"(a), "l"(b));
}

// ---------------- device scratch ----------------
__device__ float g_XW[(size_t)T_ * B_ * G_];
__device__ float g_Hst[(size_t)B_ * T_ * H_];
__device__ float g_hbuf[2][H_ * B_];
__device__ float g_bias2[G_];
__device__ int   g_tok[T_ * B_];
__device__ unsigned g_bar;                 // grid barrier counter (reset in prep)
__device__ __nv_bfloat16 g_Abig[(size_t)B_ * T_ * KBIG];   // [4096][1536] = [hi|lo|hi]
__device__ __nv_bfloat16 g_Bbig[(size_t)V_ * KBIG];        // [32000][1536] = [hi|hi|lo]

// ---------------- misc helpers ----------------
__device__ __forceinline__ uint32_t smem_u32(const void* p) {
    uint32_t a; asm("{ .reg .u64 t; cvta.to.shared.u64 t, %1; cvt.u32.u64 %0, t; }" : "=r"(a) : "l"(p));
    return a;
}
__device__ __forceinline__ uint32_t swz(uint32_t x) { return x ^ ((x >> 3) & 0x70); }
__device__ __forceinline__ void cp16(uint32_t dst, const void* src) {
    unsigned long long g;
    asm("cvta.to.global.u64 %0, %1;" : "=l"(g) : "l"(src));
    asm volatile("cp.async.cg.shared.global [%0], [%1], 16;" :: "r"(dst), "l"(g));
}
__device__ __forceinline__ void mma16816(float* c, const unsigned* a, const unsigned* b) {
    asm volatile(
        "mma.sync.aligned.m16n8k16.row.col.f32.bf16.bf16.f32 "
        "{%0,%1,%2,%3}, {%4,%5,%6,%7}, {%8,%9}, {%0,%1,%2,%3};"
        : "+f"(c[0]), "+f"(c[1]), "+f"(c[2]), "+f"(c[3])
        : "r"(a[0]), "r"(a[1]), "r"(a[2]), "r"(a[3]), "r"(b[0]), "r"(b[1]));
}

// ---------------- phase 1: prep ----------------
__global__ void prep_kernel(const void* __restrict__ target,
                            const float* __restrict__ b_ih,
                            const float* __restrict__ b_hh,
                            const float* __restrict__ enc)
{
    __shared__ int is64;
    if (threadIdx.x == 0) {
        const unsigned* w = (const unsigned*)target;
        int f = 1;
        for (int i = 1; i <= 16; ++i) if (w[2 * i + 1] != 0u) f = 0;
        is64 = f;
    }
    __syncthreads();
    if (blockIdx.x == 0 && threadIdx.x == 0) g_bar = 0u;   // deterministic per call

    const long long* t64 = (const long long*)target;
    const int*       t32 = (const int*)target;
    int tid = blockIdx.x * blockDim.x + threadIdx.x;
    int nth = gridDim.x * blockDim.x;

    for (int m = tid; m < T_ * B_; m += nth) {
        int t = m / B_, b = m % B_;
        int tok;
        if (t == 0) tok = 1;
        else tok = is64 ? (int)t64[(size_t)b * T_ + (t - 1)] : t32[(size_t)b * T_ + (t - 1)];
        g_tok[m] = tok;
    }
    for (int j = tid; j < G_; j += nth) g_bias2[j] = b_ih[j] + b_hh[j];
    for (int i = tid; i < H_ * B_; i += nth) {
        int k = i >> 5, b = i & 31;
        g_hbuf[0][i] = enc[(size_t)b * H_ + k];
    }
}

// ---------------- bf16 hi/lo conversions ----------------
__device__ __forceinline__ void split4(float4 v, ull& hiP, ull& loP) {
    union { __nv_bfloat16 h[4]; ull u; } Hh, Ll;
    float x[4] = {v.x, v.y, v.z, v.w};
#pragma unroll
    for (int j = 0; j < 4; ++j) {
        __nv_bfloat16 h = __float2bfloat16(x[j]);
        Hh.h[j] = h;
        Ll.h[j] = __float2bfloat16(x[j] - __bfloat162float(h));
    }
    hiP = Hh.u; loP = Ll.u;
}

__global__ void convB_kernel(const float* __restrict__ E) {
    size_t i4 = (size_t)blockIdx.x * blockDim.x + threadIdx.x;
    if (i4 >= (size_t)V_ * (H_ / 4)) return;
    size_t r = i4 / (H_ / 4);
    int k = (int)(i4 % (H_ / 4)) * 4;
    float4 v = *(const float4*)&E[r * H_ + k];
    ull hiP, loP; split4(v, hiP, loP);
    __nv_bfloat16* row = g_Bbig + r * KBIG;
    *(ull*)(row + k)        = hiP;   // Bhi
    *(ull*)(row + 512 + k)  = hiP;   // Bhi
    *(ull*)(row + 1024 + k) = loP;   // Blo
}

__global__ void convA_kernel() {
    size_t i4 = (size_t)blockIdx.x * blockDim.x + threadIdx.x;
    if (i4 >= (size_t)B_ * T_ * (H_ / 4)) return;
    size_t r = i4 / (H_ / 4);
    int k = (int)(i4 % (H_ / 4)) * 4;
    float4 v = *(const float4*)&g_Hst[r * H_ + k];
    ull hiP, loP; split4(v, hiP, loP);
    __nv_bfloat16* row = g_Abig + r * KBIG;
    *(ull*)(row + k)        = hiP;   // Ahi
    *(ull*)(row + 512 + k)  = loP;   // Alo
    *(ull*)(row + 1024 + k) = hiP;   // Ahi
}

// ---------------- phase 2: XW GEMM (fp32) ----------------
__global__ void __launch_bounds__(256) gemm_nt_kernel(
    const float* __restrict__ Aext, const float* __restrict__ Bm,
    int M, int N, int K)
{
    __shared__ float As[2][8][128];
    __shared__ float Bs[2][8][128];
    const float* bias = g_bias2;
    float* C = g_XW;

    int tid = threadIdx.x;
    int m0 = blockIdx.y * 128, n0 = blockIdx.x * 128;
    int lm = tid >> 1, lk = (tid & 1) * 4;

    int arow = g_tok[m0 + lm];
    const float* Ap = Aext + (size_t)arow * K + lk;
    const float* Bp = Bm + (size_t)(n0 + lm) * K + lk;

    {
        float4 va = *(const float4*)Ap;
        float4 vb = *(const float4*)Bp;
        As[0][lk + 0][lm] = va.x; As[0][lk + 1][lm] = va.y;
        As[0][lk + 2][lm] = va.z; As[0][lk + 3][lm] = va.w;
        Bs[0][lk + 0][lm] = vb.x; Bs[0][lk + 1][lm] = vb.y;
        Bs[0][lk + 2][lm] = vb.z; Bs[0][lk + 3][lm] = vb.w;
    }
    __syncthreads();

    int tx = tid & 15, ty = tid >> 4;
    ull acc[8][4];
#pragma unroll
    for (int i = 0; i < 8; ++i)
#pragma unroll
        for (int j = 0; j < 4; ++j) acc[i][j] = 0ull;

    int nstage = K / 8, buf = 0;
    for (int s = 0; s < nstage; ++s) {
        float4 va, vb;
        if (s + 1 < nstage) {
            va = *(const float4*)(Ap + (size_t)(s + 1) * 8);
            vb = *(const float4*)(Bp + (size_t)(s + 1) * 8);
        }
#pragma unroll
        for (int k = 0; k < 8; ++k) {
            float4 a0 = *(const float4*)&As[buf][k][ty * 8];
            float4 a1 = *(const float4*)&As[buf][k][ty * 8 + 4];
            float4 b0 = *(const float4*)&Bs[buf][k][tx * 4];
            float4 b1 = *(const float4*)&Bs[buf][k][tx * 4 + 64];
            ull bp0 = pk2(b0.x, b0.y), bp1 = pk2(b0.z, b0.w);
            ull bp2 = pk2(b1.x, b1.y), bp3 = pk2(b1.z, b1.w);
            float av[8] = {a0.x, a0.y, a0.z, a0.w, a1.x, a1.y, a1.z, a1.w};
#pragma unroll
            for (int i = 0; i < 8; ++i) {
                ull ad = pk2(av[i], av[i]);
                fma2(acc[i][0], ad, bp0);
                fma2(acc[i][1], ad, bp1);
                fma2(acc[i][2], ad, bp2);
                fma2(acc[i][3], ad, bp3);
            }
        }
        if (s + 1 < nstage) {
            int nb = buf ^ 1;
            As[nb][lk + 0][lm] = va.x; As[nb][lk + 1][lm] = va.y;
            As[nb][lk + 2][lm] = va.z; As[nb][lk + 3][lm] = va.w;
            Bs[nb][lk + 0][lm] = vb.x; Bs[nb][lk + 1][lm] = vb.y;
            Bs[nb][lk + 2][lm] = vb.z; Bs[nb][lk + 3][lm] = vb.w;
            __syncthreads();
            buf = nb;
        }
    }

    int nA = n0 + tx * 4;
    float bv[8];
#pragma unroll
    for (int c = 0; c < 4; ++c) { bv[c] = bias[nA + c]; bv[4 + c] = bias[nA + 64 + c]; }
#pragma unroll
    for (int i = 0; i < 8; ++i) {
        int m = m0 + ty * 8 + i;
        float r[8];
        upk2(acc[i][0], r[0], r[1]); upk2(acc[i][1], r[2], r[3]);
        upk2(acc[i][2], r[4], r[5]); upk2(acc[i][3], r[6], r[7]);
        float4 o0 = make_float4(r[0] + bv[0], r[1] + bv[1], r[2] + bv[2], r[3] + bv[3]);
        float4 o1 = make_float4(r[4] + bv[4], r[5] + bv[5], r[6] + bv[6], r[7] + bv[7]);
        *(float4*)(C + (size_t)m * N + nA)      = o0;
        *(float4*)(C + (size_t)m * N + nA + 64) = o1;
    }
}

// ---------------- phase 3: persistent LSTM recurrence (R7-proven version) ----------------
__device__ __forceinline__ float sigm(float x) { return 1.0f / (1.0f + expf(-x)); }

__global__ void __launch_bounds__(256, 1) lstm_persist_kernel(
    const float* __restrict__ W_hh, const float* __restrict__ enc)
{
    extern __shared__ float smf[];
    float2* Wd2 = (float2*)smf;            // [512][16] (64 KB)
    float*  hs  = smf + 16384;             // [512][32] (64 KB)
    float*  red = smf + 32768;             // [4][16][32] (8 KB)
    float*  gsm = smf + 34816;             // [16][32] (2 KB)

    int cta = blockIdx.x;
    int tid = threadIdx.x;
    uint32_t hsm = smem_u32(hs);

    // ---- stage W_hh rows once ----
#pragma unroll
    for (int jl = 0; jl < 16; ++jl) {
        int j = (jl >> 2) * H_ + cta * 4 + (jl & 3);
#pragma unroll
        for (int it = 0; it < 2; ++it) {
            int k = it * 256 + tid;
            float w = W_hh[(size_t)j * H_ + k];
            Wd2[k * 16 + jl] = make_float2(w, w);
        }
    }

    int q   = tid >> 6;
    int ri  = (tid >> 3) & 7;
    int ci  = tid & 7;
    int jlA = ri * 2, jlB = ri * 2 + 1;
    int b0c = ci * 4, b2c = ci * 4 + 2;

    int rjl = tid >> 4, rb0 = (tid & 15) * 2;
    int rj  = (rjl >> 2) * H_ + cta * 4 + (rjl & 3);

    int hl = tid >> 5, eb = tid & 31;
    int ek = cta * 4 + hl;
    float creg = 0.f;
    if (tid < 128) creg = enc[(size_t)eb * H_ + ek];

    for (int t = 0; t < T_; ++t) {
        float xw0 = g_XW[((size_t)t * B_ + rb0) * G_ + rj];
        float xw1 = g_XW[((size_t)t * B_ + rb0 + 1) * G_ + rj];

        // stage h in two cp.async chunks (k [0,256) then [256,512))
        {
            const float4* src = (const float4*)g_hbuf[t & 1];
#pragma unroll
            for (int i = 0; i < 8; ++i)
                cp16(hsm + (uint32_t)(tid + i * 256) * 16u, src + tid + i * 256);
            asm volatile("cp.async.commit_group;" ::: "memory");
#pragma unroll
            for (int i = 0; i < 8; ++i)
                cp16(hsm + (uint32_t)(2048 + tid + i * 256) * 16u,
                     src + 2048 + tid + i * 256);
            asm volatile("cp.async.commit_group;" ::: "memory");
        }

        ull a00 = 0, a01 = 0, a10 = 0, a11 = 0;

        asm volatile("cp.async.wait_group 1;" ::: "memory");
        __syncthreads();
        {
            int k0 = q * 64;
#pragma unroll 8
            for (int kk = 0; kk < 64; ++kk) {
                int k = k0 + kk;
                ull w0 = *(const ull*)&Wd2[k * 16 + jlA];
                ull w1 = *(const ull*)&Wd2[k * 16 + jlB];
                ull h0 = *(const ull*)&hs[k * 32 + b0c];
                ull h1 = *(const ull*)&hs[k * 32 + b2c];
                fma2(a00, h0, w0); fma2(a01, h1, w0);
                fma2(a10, h0, w1); fma2(a11, h1, w1);
            }
        }
        asm volatile("cp.async.wait_group 0;" ::: "memory");
        __syncthreads();
        {
            int k0 = 256 + q * 64;
#pragma unroll 8
            for (int kk = 0; kk < 64; ++kk) {
                int k = k0 + kk;
                ull w0 = *(const ull*)&Wd2[k * 16 + jlA];
                ull w1 = *(const ull*)&Wd2[k * 16 + jlB];
                ull h0 = *(const ull*)&hs[k * 32 + b0c];
                ull h1 = *(const ull*)&hs[k * 32 + b2c];
                fma2(a00, h0, w0); fma2(a01, h1, w0);
                fma2(a10, h0, w1); fma2(a11, h1, w1);
            }
        }

        *(ull*)&red[(q * 16 + jlA) * 32 + b0c] = a00;
        *(ull*)&red[(q * 16 + jlA) * 32 + b2c] = a01;
        *(ull*)&red[(q * 16 + jlB) * 32 + b0c] = a10;
        *(ull*)&red[(q * 16 + jlB) * 32 + b2c] = a11;
        __syncthreads();

        {
            float s0 = xw0, s1 = xw1;
#pragma unroll
            for (int qq = 0; qq < 4; ++qq) {
                float2 v = *(float2*)&red[(qq * 16 + rjl) * 32 + rb0];
                s0 += v.x; s1 += v.y;
            }
            *(float2*)&gsm[rjl * 32 + rb0] = make_float2(s0, s1);
        }
        __syncthreads();

        if (tid < 128) {
            float gi = gsm[(0 * 4 + hl) * 32 + eb];
            float gf = gsm[(1 * 4 + hl) * 32 + eb];
            float gg = gsm[(2 * 4 + hl) * 32 + eb];
            float go = gsm[(3 * 4 + hl) * 32 + eb];
            float cnew = sigm(gf) * creg + sigm(gi) * tanhf(gg);
            float hnew = sigm(go) * tanhf(cnew);
            creg = cnew;
            __stcg(&g_hbuf[(t + 1) & 1][cta * 128 + tid], hnew);
            g_Hst[((size_t)eb * T_ + t) * H_ + ek] = hnew;
        }

        __threadfence();
        __syncthreads();
        if (tid == 0) {
            unsigned arrived = atomicAdd(&g_bar, 1u) + 1u;
            unsigned target = (unsigned)NCTA_REC * (unsigned)(t + 1);
            while (arrived < target)
                arrived = *(volatile unsigned*)&g_bar;
        }
        __syncthreads();
    }
}

// ---------------- phase 4: logits via mma.sync bf16 (3-term hi/lo) ----------------
// BM=128, BN=256, BK=64, 256 threads, 8 warps (2m x 4n), 64x64 warp tiles.
// Square-ish warp tiles halve fragment LDS traffic vs 64x32 (LDS == mma bound).
#define LSTG 49152u   // per-stage: A 16KB + B 32KB
#define LNIT 24       // KBIG / 64

__device__ __forceinline__ void lstage(uint32_t sb, int buf, int s,
                                       int m0, int n0, int tid) {
    uint32_t base = (uint32_t)buf * LSTG;
#pragma unroll
    for (int i = 0; i < 4; ++i) {              // A: 1024 x 16B
        int cid = i * 256 + tid;
        int r = cid >> 3, c = cid & 7;
        cp16(sb + base + swz((uint32_t)(r * 128 + c * 16)),
             &g_Abig[(size_t)(m0 + r) * KBIG + s * 64 + c * 8]);
    }
#pragma unroll
    for (int i = 0; i < 8; ++i) {              // B: 2048 x 16B
        int cid = i * 256 + tid;
        int r = cid >> 3, c = cid & 7;
        cp16(sb + base + 16384u + swz((uint32_t)(r * 128 + c * 16)),
             &g_Bbig[(size_t)(n0 + r) * KBIG + s * 64 + c * 8]);
    }
    asm volatile("cp.async.commit_group;" ::: "memory");
}

__global__ void __launch_bounds__(256, 1) logits_mma_kernel(
    const float* __restrict__ b_out, float* __restrict__ out)
{
    extern __shared__ char smc[];
    uint32_t sb = smem_u32(smc);

    int tid = threadIdx.x;
    int lane = tid & 31, wid = tid >> 5;
    int wm = wid & 1, wn = wid >> 1;           // 2 x 4 warp grid, 64x64 tiles

    int blk = blockIdx.x;
    int nt = blk >> 5, mt = blk & 31;          // 32 m-tiles share each B n-tile
    int m0 = mt * 128, n0 = nt * 256;

    int arow = wm * 64 + ((lane >> 3) & 1) * 8 + (lane & 7);
    int akb  = ((lane >> 4) & 1) * 16;
    int brl  = lane & 15;
    int brow = wn * 64 + (brl & 7);
    int bkb  = ((brl >> 3) & 1) * 16;

    float acc[4][8][4];
#pragma unroll
    for (int i = 0; i < 4; ++i)
#pragma unroll
        for (int j = 0; j < 8; ++j)
#pragma unroll
            for (int k = 0; k < 4; ++k) acc[i][j][k] = 0.f;

    lstage(sb, 0, 0, m0, n0, tid);
    lstage(sb, 1, 1, m0, n0, tid);

    for (int s = 0; s < LNIT; ++s) {
        int buf = s % 3;
        if (s + 1 < LNIT) asm volatile("cp.async.wait_group 1;" ::: "memory");
        else              asm volatile("cp.async.wait_group 0;" ::: "memory");
        __syncthreads();
        if (s + 2 < LNIT) lstage(sb, (s + 2) % 3, s + 2, m0, n0, tid);

        uint32_t Ab = sb + (uint32_t)buf * LSTG;
        uint32_t Bb = Ab + 16384u;
#pragma unroll
        for (int ks = 0; ks < 4; ++ks) {
            unsigned af[4][4];
#pragma unroll
            for (int mf = 0; mf < 4; ++mf) {
                uint32_t a = Ab + swz((uint32_t)((arow + mf * 16) * 128 + ks * 32 + akb));
                asm volatile("ldmatrix.sync.aligned.m8n8.x4.shared.b16 {%0,%1,%2,%3}, [%4];"
                    : "=r"(af[mf][0]), "=r"(af[mf][1]), "=r"(af[mf][2]), "=r"(af[mf][3])
                    : "r"(a));
            }
            unsigned bf[8][2];
#pragma unroll
            for (int nf = 0; nf < 8; ++nf) {
                uint32_t a = Bb + swz((uint32_t)((brow + nf * 8) * 128 + ks * 32 + bkb));
                asm volatile("ldmatrix.sync.aligned.m8n8.x2.shared.b16 {%0,%1}, [%2];"
                    : "=r"(bf[nf][0]), "=r"(bf[nf][1]) : "r"(a));
            }
#pragma unroll
            for (int mf = 0; mf < 4; ++mf)
#pragma unroll
                for (int nf = 0; nf < 8; ++nf)
                    mma16816(acc[mf][nf], af[mf], bf[nf]);
        }
    }

    // epilogue: bias + float2 stores
    int ncol0 = n0 + wn * 64;
    float bv[8][2];
#pragma unroll
    for (int nf = 0; nf < 8; ++nf) {
        int c = ncol0 + nf * 8 + (lane & 3) * 2;
        bv[nf][0] = b_out[c]; bv[nf][1] = b_out[c + 1];
    }
#pragma unroll
    for (int mf = 0; mf < 4; ++mf) {
        int mrow = m0 + wm * 64 + mf * 16 + (lane >> 2);
#pragma unroll
        for (int nf = 0; nf < 8; ++nf) {
            int c = ncol0 + nf * 8 + (lane & 3) * 2;
            float2 v0 = make_float2(acc[mf][nf][0] + bv[nf][0],
                                    acc[mf][nf][1] + bv[nf][1]);
            float2 v1 = make_float2(acc[mf][nf][2] + bv[nf][0],
                                    acc[mf][nf][3] + bv[nf][1]);
            *(float2*)(out + (size_t)mrow * V_ + c)       = v0;
            *(float2*)(out + (size_t)(mrow + 8) * V_ + c) = v1;
        }
    }
}

// ---------------- launcher ----------------
extern "C" void kernel_launch(void* const* d_in, const int* in_sizes, int n_in,
                              void* d_out, int out_size)
{
    const float* enc    = (const float*)d_in[0];
    const void*  target = d_in[1];
    const float* E      = (const float*)d_in[2];
    const float* W_ih   = (const float*)d_in[3];
    const float* W_hh   = (const float*)d_in[4];
    const float* b_ih   = (const float*)d_in[5];
    const float* b_hh   = (const float*)d_in[6];
    const float* b_out  = (const float*)d_in[7];
    float* out = (float*)d_out;

    const int REC_SMEM = (16384 + 16384 + 2048 + 512) * 4;   // 141312 B
    cudaFuncSetAttribute(lstm_persist_kernel,
                         cudaFuncAttributeMaxDynamicSharedMemorySize, REC_SMEM);
    const int LOG_SMEM = 3 * (int)LSTG;                      // 147456 B
    cudaFuncSetAttribute(logits_mma_kernel,
                         cudaFuncAttributeMaxDynamicSharedMemorySize, LOG_SMEM);

    prep_kernel<<<64, 256>>>(target, b_ih, b_hh, enc);

    convB_kernel<<<(V_ * (H_ / 4) + 255) / 256, 256>>>(E);

    {
        dim3 grid(G_ / 128, (T_ * B_) / 128);
        gemm_nt_kernel<<<grid, 256>>>(E, W_ih, T_ * B_, G_, H_);
    }

    lstm_persist_kernel<<<NCTA_REC, 256, REC_SMEM>>>(W_hh, enc);

    convA_kernel<<<(B_ * T_ * (H_ / 4) + 255) / 256, 256>>>();

    logits_mma_kernel<<<32 * (V_ / 256), 256, LOG_SMEM>>>(b_out, out);
}